// round 2
// baseline (speedup 1.0000x reference)
#include <cuda_runtime.h>
#include <cuda_bf16.h>
#include <cstdint>

// PoseDisentangler: bone_len + bone_dir from H36M skeleton.
// pose_3d: (B=128, N=4096, J=17, 3) fp32, row of 51 floats per (b,n).
// out: [bone_len (B*N*16)] ++ [bone_dir (B*N*48)]
//
// HBM-bound: stage each block's rows in SMEM via exact float4 loads (input
// read once), compute per-thread, write vectorized.

#define ROWS_PER_BLOCK 128
#define ROW_FLOATS 51          // 17 joints * 3
#define NB 16                  // bones
#define EPSF 1e-12f

__global__ __launch_bounds__(ROWS_PER_BLOCK)
void pose_bones_kernel(const float* __restrict__ in,
                       float* __restrict__ len_out,
                       float* __restrict__ dir_out)
{
    __shared__ float s[ROWS_PER_BLOCK * ROW_FLOATS];   // 26112 B

    const int tid = threadIdx.x;
    const long long r0 = (long long)blockIdx.x * ROWS_PER_BLOCK;

    // Cooperative vectorized load: 128*51 floats = 1632 float4, base 16B-aligned.
    {
        const float4* __restrict__ gin =
            reinterpret_cast<const float4*>(in + r0 * ROW_FLOATS);
        float4* s4 = reinterpret_cast<float4*>(s);
        #pragma unroll
        for (int i = 0; i < 13; ++i) {                  // 13*128 = 1664 slots, 1632 used
            int idx = tid + i * ROWS_PER_BLOCK;
            if (idx < (ROWS_PER_BLOCK * ROW_FLOATS) / 4)   // 1632
                s4[idx] = gin[idx];
        }
    }
    __syncthreads();

    const float* __restrict__ p = s + tid * ROW_FLOATS;  // odd stride -> no bank conflicts

    // H36M parent of bone j (child joint j+1)
    constexpr int PARENT[NB] = {0,1,2,0,4,5,0,7,8,9,8,11,12,8,14,15};

    float lbuf[NB];
    float dbuf[NB * 3];

    #pragma unroll
    for (int j = 0; j < NB; ++j) {
        const int c  = (j + 1) * 3;
        const int pa = PARENT[j] * 3;
        float vx = p[c + 0] - p[pa + 0];
        float vy = p[c + 1] - p[pa + 1];
        float vz = p[c + 2] - p[pa + 2];
        float l  = sqrtf(vx * vx + vy * vy + vz * vz);
        float inv = 1.0f / fmaxf(l, EPSF);
        lbuf[j]         = l;
        dbuf[j * 3 + 0] = vx * inv;
        dbuf[j * 3 + 1] = vy * inv;
        dbuf[j * 3 + 2] = vz * inv;
    }

    const long long r = r0 + tid;

    // len: 16 floats at r*16 -> 64B aligned, 4x float4
    {
        float4* lo = reinterpret_cast<float4*>(len_out + r * NB);
        #pragma unroll
        for (int i = 0; i < NB / 4; ++i)
            lo[i] = make_float4(lbuf[4*i+0], lbuf[4*i+1], lbuf[4*i+2], lbuf[4*i+3]);
    }
    // dir: 48 floats at r*48 -> 16B aligned, 12x float4
    {
        float4* dout = reinterpret_cast<float4*>(dir_out + r * (NB * 3));
        #pragma unroll
        for (int i = 0; i < (NB * 3) / 4; ++i)
            dout[i] = make_float4(dbuf[4*i+0], dbuf[4*i+1], dbuf[4*i+2], dbuf[4*i+3]);
    }
}

extern "C" void kernel_launch(void* const* d_in, const int* in_sizes, int n_in,
                              void* d_out, int out_size)
{
    const float* in = (const float*)d_in[0];
    const long long rows = (long long)in_sizes[0] / ROW_FLOATS;   // B*N = 524288

    float* len_out = (float*)d_out;
    float* dir_out = len_out + rows * NB;

    const int blocks = (int)(rows / ROWS_PER_BLOCK);              // exact: 4096
    pose_bones_kernel<<<blocks, ROWS_PER_BLOCK>>>(in, len_out, dir_out);
}